// round 14
// baseline (speedup 1.0000x reference)
#include <cuda_runtime.h>
#include <cuda_fp16.h>
#include <cuda_fp8.h>
#include <math.h>

#define NB 32
#define NN 50000
#define NE 800000
#define FDIM 10

// ---- static scratch (zero at module load; every graph replay restores zeros) ----
__device__ int    g_deg[NB * NN];                     // 6.4 MB (edge-count only; self loop added in k_node)
__device__ unsigned char g_deg8[NB * NN];             // 1.6 MB (u8 degree table, gathered in k_edge)
__device__ unsigned int g_rec[(size_t)NB * NN * 4];   // 25.6 MB: 10 x fp8(e4m3) per node, 16B stride
__device__ float g_edge_sum[NB * FDIM];
__device__ float g_self_sum[NB * FDIM];

// ---------------------------------------------------------------
// K1: degree histogram over dst (int4-vectorized, streaming loads)
__global__ void k_deg(const int* __restrict__ ei) {
    int b = blockIdx.y;
    const int4* __restrict__ dst4 = (const int4*)(ei + (size_t)b * 2 * NE + NE);
    int* __restrict__ deg = g_deg + b * NN;
    int nq = NE / 4;
    int stride = gridDim.x * blockDim.x;
    for (int i = blockIdx.x * blockDim.x + threadIdx.x; i < nq; i += stride) {
        int4 d = __ldcs(dst4 + i);
        atomicAdd(&deg[d.x], 1);
        atomicAdd(&deg[d.y], 1);
        atomicAdd(&deg[d.z], 1);
        atomicAdd(&deg[d.w], 1);
    }
}

// ---------------------------------------------------------------
// block reduction of 10-component accumulator (up to 16 warps)
__device__ __forceinline__ void block_reduce10(float acc[FDIM], float* gout) {
    __shared__ float sred[16][FDIM];
    int lane = threadIdx.x & 31, warp = threadIdx.x >> 5;
    int nwarps = blockDim.x >> 5;
#pragma unroll
    for (int k = 0; k < FDIM; k++) {
        float v = acc[k];
#pragma unroll
        for (int o = 16; o > 0; o >>= 1) v += __shfl_down_sync(0xffffffffu, v, o);
        if (lane == 0) sred[warp][k] = v;
    }
    __syncthreads();
    if (warp == 0) {
#pragma unroll
        for (int k = 0; k < FDIM; k++) {
            float v = (lane < nwarps) ? sred[lane][k] : 0.f;
#pragma unroll
            for (int o = 8; o > 0; o >>= 1) v += __shfl_down_sync(0xffffffffu, v, o);
            if (lane == 0) atomicAdd(&gout[k], v);
        }
    }
}

// ---------------------------------------------------------------
// K2: 2 nodes per thread: h = xg @ W ; dinv = rsqrt(deg+1) ; rec = fp8(h*dinv) ;
//     deg8 = u8(deg+1) ; self-loop term h*dinv^2 reduced into g_self_sum.
//     Restores g_deg to zero for the next graph replay.
__global__ void k_node(const float* __restrict__ gcn_x,
                       const float* __restrict__ W) {
    __shared__ float sW[FDIM * FDIM];
    if (threadIdx.x < FDIM * FDIM) sW[threadIdx.x] = W[threadIdx.x];
    __syncthreads();

    int b = blockIdx.y;
    const float* __restrict__ xb = gcn_x + (size_t)b * NN * FDIM;
    int* __restrict__ degb = g_deg + b * NN;
    unsigned char* __restrict__ deg8b = g_deg8 + (size_t)b * NN;

    float selfacc[FDIM];
#pragma unroll
    for (int k = 0; k < FDIM; k++) selfacc[k] = 0.f;

    int npairs = NN / 2;   // 25000
    int stride = gridDim.x * blockDim.x;
    for (int p = blockIdx.x * blockDim.x + threadIdx.x; p < npairs; p += stride) {
        int n0 = 2 * p;
        float xv[20];
        const float4* xp4 = (const float4*)(xb + (size_t)n0 * FDIM);
#pragma unroll
        for (int j = 0; j < 5; j++) {
            float4 t = __ldcs(xp4 + j);
            xv[4 * j] = t.x; xv[4 * j + 1] = t.y; xv[4 * j + 2] = t.z; xv[4 * j + 3] = t.w;
        }
        int2 dg2 = *(const int2*)(degb + n0);
        int2 zero2; zero2.x = 0; zero2.y = 0;
        *(int2*)(degb + n0) = zero2;          // restore invariant for next replay
        unsigned short d8pack = 0;
#pragma unroll
        for (int u = 0; u < 2; u++) {
            const float* xu = xv + 10 * u;
            int dg = ((u == 0) ? dg2.x : dg2.y) + 1;   // + self loop
            float dinv = rsqrtf((float)dg);
            d8pack |= (unsigned short)((dg > 255 ? 255 : dg) << (8 * u));
            float d2 = dinv * dinv;
            float h[FDIM];
#pragma unroll
            for (int k = 0; k < FDIM; k++) {
                float s = 0.f;
#pragma unroll
                for (int j = 0; j < FDIM; j++) s += xu[j] * sW[j * FDIM + k];
                h[k] = s;
            }
            unsigned short p8[5];
#pragma unroll
            for (int k = 0; k < 5; k++) {
                p8[k] = __nv_cvt_float2_to_fp8x2(make_float2(h[2 * k] * dinv, h[2 * k + 1] * dinv),
                                                 __NV_SATFINITE, __NV_E4M3);
                selfacc[2 * k]     += h[2 * k] * d2;
                selfacc[2 * k + 1] += h[2 * k + 1] * d2;
            }
            uint4 v;
            v.x = (unsigned int)p8[0] | ((unsigned int)p8[1] << 16);
            v.y = (unsigned int)p8[2] | ((unsigned int)p8[3] << 16);
            v.z = (unsigned int)p8[4];
            v.w = 0u;
            *(uint4*)(g_rec + (size_t)(b * NN + n0 + u) * 4) = v;
        }
        *(unsigned short*)(deg8b + n0) = d8pack;
    }
    block_reduce10(selfacc, &g_self_sum[b * FDIM]);
}

// ---------------------------------------------------------------
__device__ __forceinline__ float2 fp8x2_to_float2(unsigned short p) {
    __half2_raw hr = __nv_cvt_fp8x2_to_halfraw2((__nv_fp8x2_storage_t)p, __NV_E4M3);
    return __half22float2(*(const __half2*)&hr);
}

// K3: edge gather-reduce: acc += rec[src] * rsqrt(deg8[dst])
//     Empirical-best config: 512 thr, 2 blocks/SM, simple loop, grid 74x32.
__global__ void __launch_bounds__(512, 2)
k_edge(const int* __restrict__ ei) {
    int b = blockIdx.y;
    const int4* __restrict__ src4 = (const int4*)(ei + (size_t)b * 2 * NE);
    const int4* __restrict__ dst4 = (const int4*)(ei + (size_t)b * 2 * NE + NE);
    const unsigned int* __restrict__ recb = g_rec + (size_t)b * NN * 4;
    const unsigned char* __restrict__ deg8b = g_deg8 + (size_t)b * NN;

    float acc[FDIM];
#pragma unroll
    for (int k = 0; k < FDIM; k++) acc[k] = 0.f;

    int nq = NE / 4;
    int stride = gridDim.x * blockDim.x;
    for (int i = blockIdx.x * blockDim.x + threadIdx.x; i < nq; i += stride) {
        int4 s4 = __ldcs(src4 + i);
        int4 d4 = __ldcs(dst4 + i);
        int ss[4] = {s4.x, s4.y, s4.z, s4.w};
        int dd[4] = {d4.x, d4.y, d4.z, d4.w};

        uint4 v[4]; float w[4];
#pragma unroll
        for (int e = 0; e < 4; e++) {
            v[e] = __ldg((const uint4*)(recb + (size_t)ss[e] * 4));
            w[e] = rsqrtf((float)__ldg(deg8b + dd[e]));
        }
#pragma unroll
        for (int e = 0; e < 4; e++) {
            float2 f0 = fp8x2_to_float2((unsigned short)(v[e].x & 0xffffu));
            float2 f1 = fp8x2_to_float2((unsigned short)(v[e].x >> 16));
            float2 f2 = fp8x2_to_float2((unsigned short)(v[e].y & 0xffffu));
            float2 f3 = fp8x2_to_float2((unsigned short)(v[e].y >> 16));
            float2 f4 = fp8x2_to_float2((unsigned short)(v[e].z & 0xffffu));
            float we = w[e];
            acc[0] += f0.x * we; acc[1] += f0.y * we;
            acc[2] += f1.x * we; acc[3] += f1.y * we;
            acc[4] += f2.x * we; acc[5] += f2.y * we;
            acc[6] += f3.x * we; acc[7] += f3.y * we;
            acc[8] += f4.x * we; acc[9] += f4.y * we;
        }
    }
    block_reduce10(acc, &g_edge_sum[b * FDIM]);
}

// ---------------------------------------------------------------
// K4: tail MLP + log_softmax. block (32 lanes, 32 batches) = 1024 threads.
//     W2 staged in smem. Zeros g_edge_sum/g_self_sum after reading (restores
//     invariant for the next graph replay — this is the last kernel).
__global__ void __launch_bounds__(1024, 1)
k_mlp(const float* __restrict__ x,
      const float* __restrict__ b_gcn,
      const float* __restrict__ W1, const float* __restrict__ b1,
      const float* __restrict__ W2, const float* __restrict__ b2,
      const float* __restrict__ Wo, const float* __restrict__ bo,
      float* __restrict__ out) {
    int b = threadIdx.y;
    int lane = threadIdx.x;
    int tid = b * 32 + lane;
    __shared__ float sW2[80 * 160];
    __shared__ float sh20[NB][20];
    __shared__ float sh80[NB][80];
    __shared__ float sh160[NB][160];
    __shared__ float sz[NB][4];

    for (int i = tid; i < 80 * 160 / 4; i += 1024)
        ((float4*)sW2)[i] = ((const float4*)W2)[i];

    if (lane < FDIM) {
        int idx = b * FDIM + lane;
        sh20[b][lane] = (g_edge_sum[idx] + g_self_sum[idx]) * (1.0f / NN) + b_gcn[lane];
        g_edge_sum[idx] = 0.f;    // restore invariant for next replay
        g_self_sum[idx] = 0.f;
    } else if (lane < 20)
        sh20[b][lane] = x[b * FDIM + (lane - 10)];
    __syncwarp();

    for (int j = lane; j < 80; j += 32) {
        float s = b1[j];
#pragma unroll
        for (int i = 0; i < 20; i++) s += sh20[b][i] * W1[i * 80 + j];
        sh80[b][j] = (s > 0.f) ? s : 0.01f * s;
    }
    __syncthreads();   // W2 staged + sh80 ready

    for (int j = lane; j < 160; j += 32) {
        float s = b2[j];
        for (int i = 0; i < 80; i++) s += sh80[b][i] * sW2[i * 160 + j];
        sh160[b][j] = (s > 0.f) ? s : 0.01f * s;
    }
    __syncwarp();

    if (lane < 4) {
        float s = bo[lane];
        for (int i = 0; i < 160; i++) s += sh160[b][i] * Wo[i * 4 + lane];
        sz[b][lane] = s;
    }
    __syncthreads();

    if (lane < 4) {
        float m = -1e30f;
#pragma unroll
        for (int bb = 0; bb < NB; bb++) m = fmaxf(m, sz[bb][lane]);
        float sum = 0.f;
#pragma unroll
        for (int bb = 0; bb < NB; bb++) sum += __expf(sz[bb][lane] - m);
        out[b * 4 + lane] = sz[b][lane] - m - logf(sum);
    }
}

// ---------------------------------------------------------------
extern "C" void kernel_launch(void* const* d_in, const int* in_sizes, int n_in,
                              void* d_out, int out_size) {
    const float* x      = (const float*)d_in[0];
    const float* gcn_x  = (const float*)d_in[1];
    const int*   ei     = (const int*)  d_in[2];
    const float* W_gcn  = (const float*)d_in[3];
    const float* b_gcn  = (const float*)d_in[4];
    const float* W1     = (const float*)d_in[5];
    const float* b1     = (const float*)d_in[6];
    const float* W2     = (const float*)d_in[7];
    const float* b2     = (const float*)d_in[8];
    const float* Wo     = (const float*)d_in[9];
    const float* bo     = (const float*)d_in[10];
    float* out = (float*)d_out;

    {
        dim3 grid(128, NB);
        k_deg<<<grid, 256>>>(ei);
    }
    {
        dim3 grid(32, NB);
        k_node<<<grid, 256>>>(gcn_x, W_gcn);
    }
    {
        dim3 grid(74, NB);   // 2368 blocks = exactly 8 waves at 2 blocks/SM
        k_edge<<<grid, 512>>>(ei);
    }
    k_mlp<<<1, dim3(32, NB)>>>(x, b_gcn, W1, b1, W2, b2, Wo, bo, out);
}

// round 15
// speedup vs baseline: 1.0910x; 1.0910x over previous
#include <cuda_runtime.h>
#include <cuda_fp16.h>
#include <cuda_fp8.h>
#include <math.h>

#define NB 32
#define NN 50000
#define NE 800000
#define FDIM 10

// ---- static scratch ----
__device__ int    g_deg[NB * NN];                     // 6.4 MB
__device__ unsigned char g_deg8[NB * NN];             // 1.6 MB (u8 degree table, gathered in k_edge)
__device__ unsigned int g_rec[(size_t)NB * NN * 4];   // 25.6 MB: 10 x fp8(e4m3) per node, 16B stride
__device__ float g_edge_sum[NB * FDIM];
__device__ float g_self_sum[NB * FDIM];
__device__ float g_z[NB * 4];                         // pre-softmax logits

// ---------------------------------------------------------------
// K0: init deg=1 (self loop) and zero accumulators. uint4-vectorized.
__global__ void k_init() {
    int i = blockIdx.x * blockDim.x + threadIdx.x;
    int total4 = (NB * NN) / 4;   // 400000
    if (i < total4) {
        uint4 one; one.x = 1u; one.y = 1u; one.z = 1u; one.w = 1u;
        ((uint4*)g_deg)[i] = one;
    }
    if (i < NB * FDIM) { g_edge_sum[i] = 0.f; g_self_sum[i] = 0.f; }
}

// ---------------------------------------------------------------
// K1: degree histogram over dst (int4-vectorized, streaming loads)
__global__ void k_deg(const int* __restrict__ ei) {
    int b = blockIdx.y;
    const int4* __restrict__ dst4 = (const int4*)(ei + (size_t)b * 2 * NE + NE);
    int* __restrict__ deg = g_deg + b * NN;
    int nq = NE / 4;
    int stride = gridDim.x * blockDim.x;
    for (int i = blockIdx.x * blockDim.x + threadIdx.x; i < nq; i += stride) {
        int4 d = __ldcs(dst4 + i);
        atomicAdd(&deg[d.x], 1);
        atomicAdd(&deg[d.y], 1);
        atomicAdd(&deg[d.z], 1);
        atomicAdd(&deg[d.w], 1);
    }
}

// ---------------------------------------------------------------
// block reduction of 10-component accumulator (up to 16 warps)
__device__ __forceinline__ void block_reduce10(float acc[FDIM], float* gout) {
    __shared__ float sred[16][FDIM];
    int lane = threadIdx.x & 31, warp = threadIdx.x >> 5;
    int nwarps = blockDim.x >> 5;
#pragma unroll
    for (int k = 0; k < FDIM; k++) {
        float v = acc[k];
#pragma unroll
        for (int o = 16; o > 0; o >>= 1) v += __shfl_down_sync(0xffffffffu, v, o);
        if (lane == 0) sred[warp][k] = v;
    }
    __syncthreads();
    if (warp == 0) {
#pragma unroll
        for (int k = 0; k < FDIM; k++) {
            float v = (lane < nwarps) ? sred[lane][k] : 0.f;
#pragma unroll
            for (int o = 8; o > 0; o >>= 1) v += __shfl_down_sync(0xffffffffu, v, o);
            if (lane == 0) atomicAdd(&gout[k], v);
        }
    }
}

// ---------------------------------------------------------------
// K2: 2 nodes per thread: h = xg @ W ; dinv = rsqrt(deg) ; rec = fp8(h*dinv) ;
//     deg8 = u8(deg) ; self-loop term h*dinv^2 reduced into g_self_sum
__global__ void k_node(const float* __restrict__ gcn_x,
                       const float* __restrict__ W) {
    __shared__ float sW[FDIM * FDIM];
    if (threadIdx.x < FDIM * FDIM) sW[threadIdx.x] = W[threadIdx.x];
    __syncthreads();

    int b = blockIdx.y;
    const float* __restrict__ xb = gcn_x + (size_t)b * NN * FDIM;
    const int* __restrict__ degb = g_deg + b * NN;
    unsigned char* __restrict__ deg8b = g_deg8 + (size_t)b * NN;

    float selfacc[FDIM];
#pragma unroll
    for (int k = 0; k < FDIM; k++) selfacc[k] = 0.f;

    int npairs = NN / 2;   // 25000
    int stride = gridDim.x * blockDim.x;
    for (int p = blockIdx.x * blockDim.x + threadIdx.x; p < npairs; p += stride) {
        int n0 = 2 * p;
        float xv[20];
        const float4* xp4 = (const float4*)(xb + (size_t)n0 * FDIM);
#pragma unroll
        for (int j = 0; j < 5; j++) {
            float4 t = __ldcs(xp4 + j);
            xv[4 * j] = t.x; xv[4 * j + 1] = t.y; xv[4 * j + 2] = t.z; xv[4 * j + 3] = t.w;
        }
        int2 dg2 = *(const int2*)(degb + n0);
        unsigned short d8pack = 0;
#pragma unroll
        for (int u = 0; u < 2; u++) {
            const float* xu = xv + 10 * u;
            int dg = (u == 0) ? dg2.x : dg2.y;
            float dinv = rsqrtf((float)dg);
            d8pack |= (unsigned short)((dg > 255 ? 255 : dg) << (8 * u));
            float d2 = dinv * dinv;
            float h[FDIM];
#pragma unroll
            for (int k = 0; k < FDIM; k++) {
                float s = 0.f;
#pragma unroll
                for (int j = 0; j < FDIM; j++) s += xu[j] * sW[j * FDIM + k];
                h[k] = s;
            }
            unsigned short p8[5];
#pragma unroll
            for (int k = 0; k < 5; k++) {
                p8[k] = __nv_cvt_float2_to_fp8x2(make_float2(h[2 * k] * dinv, h[2 * k + 1] * dinv),
                                                 __NV_SATFINITE, __NV_E4M3);
                selfacc[2 * k]     += h[2 * k] * d2;
                selfacc[2 * k + 1] += h[2 * k + 1] * d2;
            }
            uint4 v;
            v.x = (unsigned int)p8[0] | ((unsigned int)p8[1] << 16);
            v.y = (unsigned int)p8[2] | ((unsigned int)p8[3] << 16);
            v.z = (unsigned int)p8[4];
            v.w = 0u;
            *(uint4*)(g_rec + (size_t)(b * NN + n0 + u) * 4) = v;
        }
        *(unsigned short*)(deg8b + n0) = d8pack;
    }
    block_reduce10(selfacc, &g_self_sum[b * FDIM]);
}

// ---------------------------------------------------------------
__device__ __forceinline__ float2 fp8x2_to_float2(unsigned short p) {
    __half2_raw hr = __nv_cvt_fp8x2_to_halfraw2((__nv_fp8x2_storage_t)p, __NV_E4M3);
    return __half22float2(*(const __half2*)&hr);
}

// K3: edge gather-reduce: acc += rec[src] * rsqrt(deg8[dst])
//     Empirical-best config: 512 thr, 2 blocks/SM, simple loop, grid 74x32.
__global__ void __launch_bounds__(512, 2)
k_edge(const int* __restrict__ ei) {
    int b = blockIdx.y;
    const int4* __restrict__ src4 = (const int4*)(ei + (size_t)b * 2 * NE);
    const int4* __restrict__ dst4 = (const int4*)(ei + (size_t)b * 2 * NE + NE);
    const unsigned int* __restrict__ recb = g_rec + (size_t)b * NN * 4;
    const unsigned char* __restrict__ deg8b = g_deg8 + (size_t)b * NN;

    float acc[FDIM];
#pragma unroll
    for (int k = 0; k < FDIM; k++) acc[k] = 0.f;

    int nq = NE / 4;
    int stride = gridDim.x * blockDim.x;
    for (int i = blockIdx.x * blockDim.x + threadIdx.x; i < nq; i += stride) {
        int4 s4 = __ldcs(src4 + i);
        int4 d4 = __ldcs(dst4 + i);
        int ss[4] = {s4.x, s4.y, s4.z, s4.w};
        int dd[4] = {d4.x, d4.y, d4.z, d4.w};

        uint4 v[4]; float w[4];
#pragma unroll
        for (int e = 0; e < 4; e++) {
            v[e] = __ldg((const uint4*)(recb + (size_t)ss[e] * 4));
            w[e] = rsqrtf((float)__ldg(deg8b + dd[e]));
        }
#pragma unroll
        for (int e = 0; e < 4; e++) {
            float2 f0 = fp8x2_to_float2((unsigned short)(v[e].x & 0xffffu));
            float2 f1 = fp8x2_to_float2((unsigned short)(v[e].x >> 16));
            float2 f2 = fp8x2_to_float2((unsigned short)(v[e].y & 0xffffu));
            float2 f3 = fp8x2_to_float2((unsigned short)(v[e].y >> 16));
            float2 f4 = fp8x2_to_float2((unsigned short)(v[e].z & 0xffffu));
            float we = w[e];
            acc[0] += f0.x * we; acc[1] += f0.y * we;
            acc[2] += f1.x * we; acc[3] += f1.y * we;
            acc[4] += f2.x * we; acc[5] += f2.y * we;
            acc[6] += f3.x * we; acc[7] += f3.y * we;
            acc[8] += f4.x * we; acc[9] += f4.y * we;
        }
    }
    block_reduce10(acc, &g_edge_sum[b * FDIM]);
}

// ---------------------------------------------------------------
// K4a: per-batch MLP. One block per batch (32 blocks), 160 threads.
__global__ void __launch_bounds__(160, 1)
k_mlp1(const float* __restrict__ x,
       const float* __restrict__ b_gcn,
       const float* __restrict__ W1, const float* __restrict__ b1,
       const float* __restrict__ W2, const float* __restrict__ b2,
       const float* __restrict__ Wo, const float* __restrict__ bo) {
    int b = blockIdx.x;
    int t = threadIdx.x;
    __shared__ float sh20[20];
    __shared__ float sh80[80];
    __shared__ float sh160[160];

    if (t < FDIM)
        sh20[t] = (g_edge_sum[b * FDIM + t] + g_self_sum[b * FDIM + t]) * (1.0f / NN)
                  + b_gcn[t];
    else if (t < 20)
        sh20[t] = x[b * FDIM + (t - 10)];
    __syncthreads();

    if (t < 80) {
        float s = b1[t];
#pragma unroll
        for (int i = 0; i < 20; i++) s += sh20[i] * __ldg(W1 + i * 80 + t);
        sh80[t] = (s > 0.f) ? s : 0.01f * s;
    }
    __syncthreads();

    {
        float s = b2[t];
#pragma unroll 8
        for (int i = 0; i < 80; i++) s += sh80[i] * __ldg(W2 + i * 160 + t);
        sh160[t] = (s > 0.f) ? s : 0.01f * s;
    }
    __syncthreads();

    if (t < 4) {
        float s = bo[t];
#pragma unroll 8
        for (int i = 0; i < 160; i++) s += sh160[i] * __ldg(Wo + i * 4 + t);
        g_z[b * 4 + t] = s;
    }
}

// K4b: log_softmax over batch axis (32x4 logits). One tiny block.
__global__ void k_mlp2(float* __restrict__ out) {
    __shared__ float sz[NB * 4];
    int t = threadIdx.x;   // 128 threads: b = t/4, c = t%4
    sz[t] = g_z[t];
    __syncthreads();
    int c = t & 3;
    float m = -1e30f;
#pragma unroll
    for (int bb = 0; bb < NB; bb++) m = fmaxf(m, sz[bb * 4 + c]);
    float sum = 0.f;
#pragma unroll
    for (int bb = 0; bb < NB; bb++) sum += __expf(sz[bb * 4 + c] - m);
    out[t] = sz[t] - m - logf(sum);
}

// ---------------------------------------------------------------
extern "C" void kernel_launch(void* const* d_in, const int* in_sizes, int n_in,
                              void* d_out, int out_size) {
    const float* x      = (const float*)d_in[0];
    const float* gcn_x  = (const float*)d_in[1];
    const int*   ei     = (const int*)  d_in[2];
    const float* W_gcn  = (const float*)d_in[3];
    const float* b_gcn  = (const float*)d_in[4];
    const float* W1     = (const float*)d_in[5];
    const float* b1     = (const float*)d_in[6];
    const float* W2     = (const float*)d_in[7];
    const float* b2     = (const float*)d_in[8];
    const float* Wo     = (const float*)d_in[9];
    const float* bo     = (const float*)d_in[10];
    float* out = (float*)d_out;

    {
        int total4 = (NB * NN) / 4;
        int threads = 256;
        k_init<<<(total4 + threads - 1) / threads, threads>>>();
    }
    {
        dim3 grid(128, NB);
        k_deg<<<grid, 256>>>(ei);
    }
    {
        dim3 grid(32, NB);
        k_node<<<grid, 256>>>(gcn_x, W_gcn);
    }
    {
        dim3 grid(74, NB);   // 2368 blocks = exactly 8 waves at 2 blocks/SM
        k_edge<<<grid, 512>>>(ei);
    }
    k_mlp1<<<NB, 160>>>(x, b_gcn, W1, b1, W2, b2, Wo, bo);
    k_mlp2<<<1, 128>>>(out);
}

// round 16
// speedup vs baseline: 1.0974x; 1.0059x over previous
#include <cuda_runtime.h>
#include <cuda_fp16.h>
#include <cuda_fp8.h>
#include <math.h>

#define NB 32
#define NN 50000
#define NE 800000
#define FDIM 10

// ---- static scratch ----
__device__ int    g_deg[NB * NN];                     // 6.4 MB
__device__ unsigned char g_deg8[NB * NN];             // 1.6 MB (u8 degree table, gathered in k_edge)
__device__ unsigned int g_rec[(size_t)NB * NN * 4];   // 25.6 MB: 10 x fp8(e4m3) per node, 16B stride
__device__ float g_edge_sum[NB * FDIM];
__device__ float g_self_sum[NB * FDIM];
__device__ float g_z[NB * 4];                         // pre-softmax logits

// packed f32x2 helpers (sm_10x)
__device__ __forceinline__ unsigned long long pack2(float lo, float hi) {
    unsigned long long r;
    asm("mov.b64 %0, {%1, %2};" : "=l"(r) : "f"(lo), "f"(hi));
    return r;
}
__device__ __forceinline__ void unpack2(unsigned long long p, float& lo, float& hi) {
    asm("mov.b64 {%0, %1}, %2;" : "=f"(lo), "=f"(hi) : "l"(p));
}
__device__ __forceinline__ unsigned long long fma2(unsigned long long a,
                                                   unsigned long long b,
                                                   unsigned long long c) {
    unsigned long long d;
    asm("fma.rn.f32x2 %0, %1, %2, %3;" : "=l"(d) : "l"(a), "l"(b), "l"(c));
    return d;
}
__device__ __forceinline__ unsigned long long mul2(unsigned long long a,
                                                   unsigned long long b) {
    unsigned long long d;
    asm("mul.rn.f32x2 %0, %1, %2;" : "=l"(d) : "l"(a), "l"(b));
    return d;
}

// ---------------------------------------------------------------
// K0: init deg=1 (self loop) and zero accumulators. uint4-vectorized.
__global__ void k_init() {
    int i = blockIdx.x * blockDim.x + threadIdx.x;
    int total4 = (NB * NN) / 4;   // 400000
    if (i < total4) {
        uint4 one; one.x = 1u; one.y = 1u; one.z = 1u; one.w = 1u;
        ((uint4*)g_deg)[i] = one;
    }
    if (i < NB * FDIM) { g_edge_sum[i] = 0.f; g_self_sum[i] = 0.f; }
}

// ---------------------------------------------------------------
// K1: degree histogram over dst (int4-vectorized, streaming loads)
__global__ void k_deg(const int* __restrict__ ei) {
    int b = blockIdx.y;
    const int4* __restrict__ dst4 = (const int4*)(ei + (size_t)b * 2 * NE + NE);
    int* __restrict__ deg = g_deg + b * NN;
    int nq = NE / 4;
    int stride = gridDim.x * blockDim.x;
    for (int i = blockIdx.x * blockDim.x + threadIdx.x; i < nq; i += stride) {
        int4 d = __ldcs(dst4 + i);
        atomicAdd(&deg[d.x], 1);
        atomicAdd(&deg[d.y], 1);
        atomicAdd(&deg[d.z], 1);
        atomicAdd(&deg[d.w], 1);
    }
}

// ---------------------------------------------------------------
// block reduction of 10-component accumulator (up to 16 warps)
__device__ __forceinline__ void block_reduce10(float acc[FDIM], float* gout) {
    __shared__ float sred[16][FDIM];
    int lane = threadIdx.x & 31, warp = threadIdx.x >> 5;
    int nwarps = blockDim.x >> 5;
#pragma unroll
    for (int k = 0; k < FDIM; k++) {
        float v = acc[k];
#pragma unroll
        for (int o = 16; o > 0; o >>= 1) v += __shfl_down_sync(0xffffffffu, v, o);
        if (lane == 0) sred[warp][k] = v;
    }
    __syncthreads();
    if (warp == 0) {
#pragma unroll
        for (int k = 0; k < FDIM; k++) {
            float v = (lane < nwarps) ? sred[lane][k] : 0.f;
#pragma unroll
            for (int o = 8; o > 0; o >>= 1) v += __shfl_down_sync(0xffffffffu, v, o);
            if (lane == 0) atomicAdd(&gout[k], v);
        }
    }
}

// ---------------------------------------------------------------
// K2: 2 nodes per thread; matmul via packed f32x2 FMA (output pairs).
//     rec = fp8(h*dinv) (16B) ; deg8 = u8(deg) ; selfacc += h*dinv^2 (packed).
__global__ void k_node(const float* __restrict__ gcn_x,
                       const float* __restrict__ W) {
    // sW2[j*5+k2] = (W[j][2k2], W[j][2k2+1])
    __shared__ float2 sW2[FDIM * 5];
    if (threadIdx.x < FDIM * 5) {
        int j = threadIdx.x / 5, k2 = threadIdx.x % 5;
        sW2[threadIdx.x] = make_float2(W[j * FDIM + 2 * k2], W[j * FDIM + 2 * k2 + 1]);
    }
    __syncthreads();

    int b = blockIdx.y;
    const float* __restrict__ xb = gcn_x + (size_t)b * NN * FDIM;
    const int* __restrict__ degb = g_deg + b * NN;
    unsigned char* __restrict__ deg8b = g_deg8 + (size_t)b * NN;

    unsigned long long sacc[5];
#pragma unroll
    for (int k = 0; k < 5; k++) sacc[k] = 0ull;

    int npairs = NN / 2;   // 25000
    int stride = gridDim.x * blockDim.x;
    for (int p = blockIdx.x * blockDim.x + threadIdx.x; p < npairs; p += stride) {
        int n0 = 2 * p;
        float xv[20];
        const float4* xp4 = (const float4*)(xb + (size_t)n0 * FDIM);
#pragma unroll
        for (int j = 0; j < 5; j++) {
            float4 t = __ldcs(xp4 + j);
            xv[4 * j] = t.x; xv[4 * j + 1] = t.y; xv[4 * j + 2] = t.z; xv[4 * j + 3] = t.w;
        }
        int2 dg2 = *(const int2*)(degb + n0);
        unsigned short d8pack = 0;
#pragma unroll
        for (int u = 0; u < 2; u++) {
            const float* xu = xv + 10 * u;
            int dg = (u == 0) ? dg2.x : dg2.y;
            float dinv = rsqrtf((float)dg);
            d8pack |= (unsigned short)((dg > 255 ? 255 : dg) << (8 * u));
            float d2 = dinv * dinv;

            unsigned long long hp[5];
#pragma unroll
            for (int k = 0; k < 5; k++) hp[k] = 0ull;
#pragma unroll
            for (int j = 0; j < FDIM; j++) {
                unsigned long long xp = pack2(xu[j], xu[j]);
#pragma unroll
                for (int k = 0; k < 5; k++) {
                    unsigned long long wp = *(const unsigned long long*)&sW2[j * 5 + k];
                    hp[k] = fma2(xp, wp, hp[k]);
                }
            }
            unsigned long long dp  = pack2(dinv, dinv);
            unsigned long long d2p = pack2(d2, d2);
            unsigned short p8[5];
#pragma unroll
            for (int k = 0; k < 5; k++) {
                unsigned long long gp_ = mul2(hp[k], dp);
                float g0, g1; unpack2(gp_, g0, g1);
                p8[k] = __nv_cvt_float2_to_fp8x2(make_float2(g0, g1),
                                                 __NV_SATFINITE, __NV_E4M3);
                sacc[k] = fma2(hp[k], d2p, sacc[k]);
            }
            uint4 v;
            v.x = (unsigned int)p8[0] | ((unsigned int)p8[1] << 16);
            v.y = (unsigned int)p8[2] | ((unsigned int)p8[3] << 16);
            v.z = (unsigned int)p8[4];
            v.w = 0u;
            *(uint4*)(g_rec + (size_t)(b * NN + n0 + u) * 4) = v;
        }
        *(unsigned short*)(deg8b + n0) = d8pack;
    }

    float selfacc[FDIM];
#pragma unroll
    for (int k = 0; k < 5; k++) unpack2(sacc[k], selfacc[2 * k], selfacc[2 * k + 1]);
    block_reduce10(selfacc, &g_self_sum[b * FDIM]);
}

// ---------------------------------------------------------------
__device__ __forceinline__ float2 fp8x2_to_float2(unsigned short p) {
    __half2_raw hr = __nv_cvt_fp8x2_to_halfraw2((__nv_fp8x2_storage_t)p, __NV_E4M3);
    return __half22float2(*(const __half2*)&hr);
}

// K3: edge gather-reduce: acc += rec[src] * rsqrt(deg8[dst])
//     Empirical-best config: 512 thr, 2 blocks/SM, simple loop, grid 74x32.
__global__ void __launch_bounds__(512, 2)
k_edge(const int* __restrict__ ei) {
    int b = blockIdx.y;
    const int4* __restrict__ src4 = (const int4*)(ei + (size_t)b * 2 * NE);
    const int4* __restrict__ dst4 = (const int4*)(ei + (size_t)b * 2 * NE + NE);
    const unsigned int* __restrict__ recb = g_rec + (size_t)b * NN * 4;
    const unsigned char* __restrict__ deg8b = g_deg8 + (size_t)b * NN;

    float acc[FDIM];
#pragma unroll
    for (int k = 0; k < FDIM; k++) acc[k] = 0.f;

    int nq = NE / 4;
    int stride = gridDim.x * blockDim.x;
    for (int i = blockIdx.x * blockDim.x + threadIdx.x; i < nq; i += stride) {
        int4 s4 = __ldcs(src4 + i);
        int4 d4 = __ldcs(dst4 + i);
        int ss[4] = {s4.x, s4.y, s4.z, s4.w};
        int dd[4] = {d4.x, d4.y, d4.z, d4.w};

        uint4 v[4]; float w[4];
#pragma unroll
        for (int e = 0; e < 4; e++) {
            v[e] = __ldg((const uint4*)(recb + (size_t)ss[e] * 4));
            w[e] = rsqrtf((float)__ldg(deg8b + dd[e]));
        }
#pragma unroll
        for (int e = 0; e < 4; e++) {
            float2 f0 = fp8x2_to_float2((unsigned short)(v[e].x & 0xffffu));
            float2 f1 = fp8x2_to_float2((unsigned short)(v[e].x >> 16));
            float2 f2 = fp8x2_to_float2((unsigned short)(v[e].y & 0xffffu));
            float2 f3 = fp8x2_to_float2((unsigned short)(v[e].y >> 16));
            float2 f4 = fp8x2_to_float2((unsigned short)(v[e].z & 0xffffu));
            float we = w[e];
            acc[0] += f0.x * we; acc[1] += f0.y * we;
            acc[2] += f1.x * we; acc[3] += f1.y * we;
            acc[4] += f2.x * we; acc[5] += f2.y * we;
            acc[6] += f3.x * we; acc[7] += f3.y * we;
            acc[8] += f4.x * we; acc[9] += f4.y * we;
        }
    }
    block_reduce10(acc, &g_edge_sum[b * FDIM]);
}

// ---------------------------------------------------------------
// K4a: per-batch MLP. One block per batch (32 blocks), 160 threads.
__global__ void __launch_bounds__(160, 1)
k_mlp1(const float* __restrict__ x,
       const float* __restrict__ b_gcn,
       const float* __restrict__ W1, const float* __restrict__ b1,
       const float* __restrict__ W2, const float* __restrict__ b2,
       const float* __restrict__ Wo, const float* __restrict__ bo) {
    int b = blockIdx.x;
    int t = threadIdx.x;
    __shared__ float sh20[20];
    __shared__ float sh80[80];
    __shared__ float sh160[160];

    if (t < FDIM)
        sh20[t] = (g_edge_sum[b * FDIM + t] + g_self_sum[b * FDIM + t]) * (1.0f / NN)
                  + b_gcn[t];
    else if (t < 20)
        sh20[t] = x[b * FDIM + (t - 10)];
    __syncthreads();

    if (t < 80) {
        float s = b1[t];
#pragma unroll
        for (int i = 0; i < 20; i++) s += sh20[i] * __ldg(W1 + i * 80 + t);
        sh80[t] = (s > 0.f) ? s : 0.01f * s;
    }
    __syncthreads();

    {
        float s = b2[t];
#pragma unroll 8
        for (int i = 0; i < 80; i++) s += sh80[i] * __ldg(W2 + i * 160 + t);
        sh160[t] = (s > 0.f) ? s : 0.01f * s;
    }
    __syncthreads();

    if (t < 4) {
        float s = bo[t];
#pragma unroll 8
        for (int i = 0; i < 160; i++) s += sh160[i] * __ldg(Wo + i * 4 + t);
        g_z[b * 4 + t] = s;
    }
}

// K4b: log_softmax over batch axis (32x4 logits). One tiny block.
__global__ void k_mlp2(float* __restrict__ out) {
    __shared__ float sz[NB * 4];
    int t = threadIdx.x;   // 128 threads: b = t/4, c = t%4
    sz[t] = g_z[t];
    __syncthreads();
    int c = t & 3;
    float m = -1e30f;
#pragma unroll
    for (int bb = 0; bb < NB; bb++) m = fmaxf(m, sz[bb * 4 + c]);
    float sum = 0.f;
#pragma unroll
    for (int bb = 0; bb < NB; bb++) sum += __expf(sz[bb * 4 + c] - m);
    out[t] = sz[t] - m - logf(sum);
}

// ---------------------------------------------------------------
extern "C" void kernel_launch(void* const* d_in, const int* in_sizes, int n_in,
                              void* d_out, int out_size) {
    const float* x      = (const float*)d_in[0];
    const float* gcn_x  = (const float*)d_in[1];
    const int*   ei     = (const int*)  d_in[2];
    const float* W_gcn  = (const float*)d_in[3];
    const float* b_gcn  = (const float*)d_in[4];
    const float* W1     = (const float*)d_in[5];
    const float* b1     = (const float*)d_in[6];
    const float* W2     = (const float*)d_in[7];
    const float* b2     = (const float*)d_in[8];
    const float* Wo     = (const float*)d_in[9];
    const float* bo     = (const float*)d_in[10];
    float* out = (float*)d_out;

    {
        int total4 = (NB * NN) / 4;
        int threads = 256;
        k_init<<<(total4 + threads - 1) / threads, threads>>>();
    }
    {
        dim3 grid(128, NB);
        k_deg<<<grid, 256>>>(ei);
    }
    {
        dim3 grid(32, NB);
        k_node<<<grid, 256>>>(gcn_x, W_gcn);
    }
    {
        dim3 grid(74, NB);   // 2368 blocks = exactly 8 waves at 2 blocks/SM
        k_edge<<<grid, 512>>>(ei);
    }
    k_mlp1<<<NB, 160>>>(x, b_gcn, W1, b1, W2, b2, Wo, bo);
    k_mlp2<<<1, 128>>>(out);
}